// round 16
// baseline (speedup 1.0000x reference)
#include <cuda_runtime.h>
#include <cuda_bf16.h>
#include <cstdint>
#include <cstddef>

#define Bn   32
#define Vn   256
#define En   4
#define Mn   16
#define U1n  128
#define F1n  144      // M + U1
#define U2n  64
#define F2n  80       // U2 + M
#define AUXn 128
#define L1n  256
#define L2n  256
#define EMBn 266240   // E*V*V + V*M
#define BEMB ((size_t)Bn*EMBn)

typedef unsigned long long ull;

// ---------------- scratch (static device memory; no allocs) ----------------
__device__ float g_ann1 [Bn*Vn*F1n];      // [b][v][ node(16) | h0(128) ]
__device__ float g_P1   [Bn*En*Vn*U2n];   // per-edge projected features
__device__ float g_ann2 [Bn*Vn*F2n];      // [b][v][ h1(64) | node(16) ]
__device__ float g_poolp[8*Bn*AUXn];      // pooling partial sums (8 v-chunks)
__device__ float g_o2   [Bn*L2n];         // dense head output

__device__ __forceinline__ float sigmoidf_(float x){ return 1.0f/(1.0f+expf(-x)); }

__device__ __forceinline__ ull fma2_(ull a, ull b, ull c){
  ull d;
  asm("fma.rn.f32x2 %0, %1, %2, %3;" : "=l"(d) : "l"(a), "l"(b), "l"(c));
  return d;
}
__device__ __forceinline__ ull dup2_(float v){
  ull d;
  asm("mov.b64 %0, {%1, %1};" : "=l"(d) : "f"(v));
  return d;
}

// ---------------- K1: GCL layer 0 (reformulated) ---------------------------
// out[v,u] = (adj^T [node|1])[v,(e,f)] @ [W0;b0][(e,f),u] + node@W2_0 + b2_0
// grid (8, B), block 256
__global__ void k1_gcl0(const float* __restrict__ adj, const float* __restrict__ node,
                        const float* __restrict__ W0,  const float* __restrict__ b0,
                        const float* __restrict__ W2,  const float* __restrict__ b2){
  extern __shared__ float sm[];
  float* sNode = sm;                 // 256*17  (node + ones column)
  float* sW    = sNode + Vn*17;      // 68*128
  float* sW2   = sW    + 68*U1n;     // 16*128
  float* sB2   = sW2   + Mn*U1n;     // 128
  float* sAdj  = sB2   + U1n;        // 32*257 (padded)
  float* sA2   = sAdj  + 32*257;     // 32*68
  const int tid = threadIdx.x;
  const int b = blockIdx.y, v0 = blockIdx.x*32;

  for (int idx = tid; idx < Vn*17; idx += 256){
    int v = idx/17, f = idx - v*17;
    sNode[idx] = (f < Mn) ? node[((size_t)b*Vn+v)*Mn + f] : 1.0f;
  }
  for (int idx = tid; idx < 68*U1n; idx += 256){
    int k = idx >> 7, u = idx & 127;
    int e = k/17, f = k - e*17;
    sW[idx] = (f < Mn) ? W0[((size_t)e*Mn+f)*U1n + u] : b0[e*U1n + u];
  }
  for (int idx = tid; idx < Mn*U1n; idx += 256) sW2[idx] = W2[idx];
  for (int idx = tid; idx < U1n;    idx += 256) sB2[idx] = b2[idx];
  __syncthreads();

  for (int e = 0; e < En; ++e){
    for (int idx = tid; idx < 32*Vn; idx += 256){
      int vl = idx >> 8, w = idx & 255;
      sAdj[vl*257 + w] = adj[(((size_t)b*(En+1) + e)*Vn + (v0+vl))*(size_t)Vn + w];
    }
    __syncthreads();
    for (int idx = tid; idx < 32*17; idx += 256){
      int vl = idx/17, f = idx - vl*17;
      const float* arow = sAdj + vl*257;
      float acc = 0.f;
      #pragma unroll 8
      for (int w = 0; w < Vn; ++w) acc += arow[w]*sNode[w*17+f];
      sA2[vl*68 + e*17 + f] = acc;
    }
    __syncthreads();
  }

  // main GEMM: 16 contiguous u per thread, packed f32x2
  const int ug = tid & 7, vl = tid >> 3;
  ull acc[8];
  const float2* b2p = (const float2*)sB2;
  #pragma unroll
  for (int i = 0; i < 8; ++i) acc[i] = ((const ull*)&b2p[ug*8 + i])[0];
  const float* a2 = sA2 + vl*68;
  for (int k = 0; k < 68; ++k){
    ull a = dup2_(a2[k]);
    const float4* wr = (const float4*)(sW + k*U1n + ug*16);
    #pragma unroll
    for (int q = 0; q < 4; ++q){
      float4 w4 = wr[q];
      acc[2*q]   = fma2_(a, ((ull*)&w4)[0], acc[2*q]);
      acc[2*q+1] = fma2_(a, ((ull*)&w4)[1], acc[2*q+1]);
    }
  }
  const float* nr = sNode + (v0+vl)*17;
  #pragma unroll
  for (int f = 0; f < Mn; ++f){
    ull a = dup2_(nr[f]);
    const float4* wr = (const float4*)(sW2 + f*U1n + ug*16);
    #pragma unroll
    for (int q = 0; q < 4; ++q){
      float4 w4 = wr[q];
      acc[2*q]   = fma2_(a, ((ull*)&w4)[0], acc[2*q]);
      acc[2*q+1] = fma2_(a, ((ull*)&w4)[1], acc[2*q+1]);
    }
  }
  float* dst = g_ann1 + ((size_t)b*Vn + v0+vl)*F1n + Mn + ug*16;
  #pragma unroll
  for (int i = 0; i < 8; ++i){
    float2 p = *(float2*)&acc[i];
    float2 r; r.x = tanhf(p.x); r.y = tanhf(p.y);
    ((float2*)dst)[i] = r;
  }
  for (int idx = tid; idx < 32*Mn; idx += 256){
    int v = idx >> 4, f = idx & 15;
    g_ann1[((size_t)b*Vn + v0+v)*F1n + f] = sNode[(v0+v)*17 + f];
  }
}

// ---------------- K2: P1[b,e,w,:] = ann1[b,w,:] @ W_adj1[e] + b_adj1[e] ----
// grid (16 = 4wc x En, B), block 256
__global__ void k2_p1(const float* __restrict__ W1, const float* __restrict__ b1){
  extern __shared__ float sm[];
  float* sW1  = sm;                 // 144*64
  float* sB1  = sW1 + F1n*U2n;      // 64
  float* sAnn = sB1 + U2n;          // 64*145 (padded)
  const int tid = threadIdx.x;
  const int wc = blockIdx.x & 3, e = blockIdx.x >> 2, b = blockIdx.y;
  for (int idx = tid; idx < F1n*U2n; idx += 256) sW1[idx] = W1[(size_t)e*F1n*U2n + idx];
  for (int idx = tid; idx < U2n;     idx += 256) sB1[idx] = b1[e*U2n + idx];
  for (int idx = tid; idx < 64*F1n;  idx += 256){
    int w = idx/F1n, f = idx - w*F1n;
    sAnn[w*145 + f] = g_ann1[((size_t)b*Vn + wc*64 + w)*F1n + f];
  }
  __syncthreads();
  const int ug = tid & 3, wl = tid >> 2;   // 16 contiguous u per thread
  ull acc[8];
  const float2* b1p = (const float2*)sB1;
  #pragma unroll
  for (int i = 0; i < 8; ++i) acc[i] = ((const ull*)&b1p[ug*8 + i])[0];
  const float* ar = sAnn + wl*145;
  for (int f = 0; f < F1n; ++f){
    ull a = dup2_(ar[f]);
    const float4* wr = (const float4*)(sW1 + f*U2n + ug*16);
    #pragma unroll
    for (int q = 0; q < 4; ++q){
      float4 w4 = wr[q];
      acc[2*q]   = fma2_(a, ((ull*)&w4)[0], acc[2*q]);
      acc[2*q+1] = fma2_(a, ((ull*)&w4)[1], acc[2*q+1]);
    }
  }
  float* dst = g_P1 + (((size_t)b*En + e)*Vn + wc*64 + wl)*U2n + ug*16;
  #pragma unroll
  for (int i = 0; i < 8; ++i) ((float2*)dst)[i] = *(float2*)&acc[i];
}

// ---------------- K3: GCL layer 1 contraction + W2 term + concat -> ann2 ---
// grid (8, B), block 256
__global__ void k3_gcl1(const float* __restrict__ adj, const float* __restrict__ node,
                        const float* __restrict__ W2,  const float* __restrict__ b2){
  extern __shared__ float sm[];
  float* sAdj = sm;               // 32*257 (padded)
  float* sP   = sAdj + 32*257;    // 64*64
  float* sW2  = sP   + 64*64;     // 144*64
  float* sB2  = sW2  + F1n*U2n;   // 64
  float* sAnn = sB2  + U2n;       // 32*145 (padded)
  const int tid = threadIdx.x;
  const int b = blockIdx.y, v0 = blockIdx.x*32;
  for (int idx = tid; idx < F1n*U2n; idx += 256) sW2[idx] = W2[idx];
  for (int idx = tid; idx < U2n;     idx += 256) sB2[idx] = b2[idx];
  for (int idx = tid; idx < 32*F1n;  idx += 256){
    int vl = idx/F1n, f = idx - vl*F1n;
    sAnn[vl*145+f] = g_ann1[((size_t)b*Vn + v0+vl)*F1n + f];
  }
  __syncthreads();
  const int ug = tid & 7, vl = tid >> 3;   // 8 contiguous u per thread
  ull acc[4];
  const float2* b2p = (const float2*)sB2;
  #pragma unroll
  for (int i = 0; i < 4; ++i) acc[i] = ((const ull*)&b2p[ug*4 + i])[0];
  const float* ar = sAnn + vl*145;
  for (int f = 0; f < F1n; ++f){
    ull a = dup2_(ar[f]);
    const float4* wr = (const float4*)(sW2 + f*U2n + ug*8);
    #pragma unroll
    for (int q = 0; q < 2; ++q){
      float4 w4 = wr[q];
      acc[2*q]   = fma2_(a, ((ull*)&w4)[0], acc[2*q]);
      acc[2*q+1] = fma2_(a, ((ull*)&w4)[1], acc[2*q+1]);
    }
  }
  for (int e = 0; e < En; ++e){
    for (int idx = tid; idx < 32*Vn; idx += 256){
      int v = idx >> 8, w = idx & 255;
      sAdj[v*257+w] = adj[(((size_t)b*(En+1)+e)*Vn + v0+v)*(size_t)Vn + w];
    }
    __syncthreads();
    for (int wc = 0; wc < 4; ++wc){
      for (int idx = tid; idx < 64*U2n; idx += 256)
        sP[idx] = g_P1[(((size_t)b*En + e)*Vn + wc*64)*U2n + idx];
      __syncthreads();
      const float* arow = sAdj + vl*257 + wc*64;
      #pragma unroll 4
      for (int w = 0; w < 64; ++w){
        ull a = dup2_(arow[w]);
        const float4* pr = (const float4*)(sP + w*U2n + ug*8);
        float4 p0 = pr[0], p1 = pr[1];
        acc[0] = fma2_(a, ((ull*)&p0)[0], acc[0]);
        acc[1] = fma2_(a, ((ull*)&p0)[1], acc[1]);
        acc[2] = fma2_(a, ((ull*)&p1)[0], acc[2]);
        acc[3] = fma2_(a, ((ull*)&p1)[1], acc[3]);
      }
      __syncthreads();
    }
  }
  float* dst = g_ann2 + ((size_t)b*Vn + v0+vl)*F2n + ug*8;
  #pragma unroll
  for (int i = 0; i < 4; ++i){
    float2 p = *(float2*)&acc[i];
    float2 r; r.x = tanhf(p.x); r.y = tanhf(p.y);
    ((float2*)dst)[i] = r;
  }
  for (int idx = tid; idx < 32*Mn; idx += 256){
    int v = idx >> 4, f = idx & 15;
    g_ann2[((size_t)b*Vn + v0+v)*F2n + U2n + f] = node[((size_t)b*Vn + v0+v)*Mn + f];
  }
}

// ---------------- K4: gated pooling, packed f32x2, 8 v-chunks --------------
// grid (8, B), block 256
__global__ void k4_pool(const float* __restrict__ Wi, const float* __restrict__ bi,
                        const float* __restrict__ Wj, const float* __restrict__ bj){
  extern __shared__ ull smu[];
  ull* sWi2  = smu;                 // 80*64
  ull* sWj2  = sWi2 + F2n*64;       // 80*64
  ull* sbi2  = sWj2 + F2n*64;       // 64
  ull* sbj2  = sbi2 + 64;           // 64
  ull* sAnn2 = sbj2 + 64;           // 32*80 (duplicated pairs)
  float2* sRed = (float2*)(sAnn2 + 32*F2n);  // 4*64
  const int tid = threadIdx.x;
  const int vc = blockIdx.x, b = blockIdx.y;
  for (int idx = tid; idx < F2n*64; idx += 256){
    sWi2[idx] = ((const ull*)Wi)[idx];
    sWj2[idx] = ((const ull*)Wj)[idx];
  }
  if (tid < 64){ sbi2[tid] = ((const ull*)bi)[tid]; sbj2[tid] = ((const ull*)bj)[tid]; }
  for (int idx = tid; idx < 32*F2n; idx += 256){
    int v = idx/F2n, f = idx - v*F2n;
    sAnn2[idx] = dup2_(g_ann2[((size_t)b*Vn + vc*32 + v)*F2n + f]);
  }
  __syncthreads();
  const int ul = tid & 63, vg = tid >> 6;   // 64 aux-pairs x 4 v-groups(8 v)
  ull si[8], sj[8];
  #pragma unroll
  for (int j = 0; j < 8; ++j){ si[j] = sbi2[ul]; sj[j] = sbj2[ul]; }
  const ull* annb = sAnn2 + vg*8*F2n;
  for (int f = 0; f < F2n; ++f){
    ull wi = sWi2[f*64 + ul], wj = sWj2[f*64 + ul];
    #pragma unroll
    for (int j = 0; j < 8; ++j){
      ull a = annb[j*F2n + f];
      si[j] = fma2_(a, wi, si[j]);
      sj[j] = fma2_(a, wj, sj[j]);
    }
  }
  float2 pool = make_float2(0.f, 0.f);
  #pragma unroll
  for (int j = 0; j < 8; ++j){
    float2 pi = *(float2*)&si[j];
    float2 pj = *(float2*)&sj[j];
    pool.x += sigmoidf_(pi.x) * tanhf(pj.x);
    pool.y += sigmoidf_(pi.y) * tanhf(pj.y);
  }
  sRed[vg*64 + ul] = pool;
  __syncthreads();
  if (tid < 64){
    float2 s = sRed[tid];
    #pragma unroll
    for (int g = 1; g < 4; ++g){
      float2 t = sRed[g*64 + tid];
      s.x += t.x; s.y += t.y;
    }
    ((float2*)(g_poolp + ((size_t)vc*Bn + b)*AUXn))[tid] = s;
  }
}

// ---------------- K5: dense head (o -> tanh -> d1 -> d2) -------------------
// grid B, block 256
__global__ void k5_dense(const float* __restrict__ Wd1, const float* __restrict__ bd1,
                         const float* __restrict__ Wd2, const float* __restrict__ bd2){
  __shared__ float so [AUXn];
  __shared__ float so1[L1n];
  const int tid = threadIdx.x, b = blockIdx.x;
  if (tid < AUXn){
    float s = 0.f;
    #pragma unroll
    for (int vc = 0; vc < 8; ++vc) s += g_poolp[((size_t)vc*Bn + b)*AUXn + tid];
    so[tid] = tanhf(s);
  }
  __syncthreads();
  float acc = bd1[tid];
  #pragma unroll 4
  for (int k = 0; k < AUXn; ++k) acc += so[k]*Wd1[k*L1n + tid];
  so1[tid] = tanhf(acc);
  __syncthreads();
  acc = bd2[tid];
  #pragma unroll 4
  for (int k = 0; k < L1n; ++k) acc += so1[k]*Wd2[k*L2n + tid];
  g_o2[b*L2n + tid] = tanhf(acc);
}

// ---------------- K6a: mu = o2 @ Wmu + bmu ---------------------------------
// grid EMB/256 = 1040, block 256, smem 64KB, 3 CTAs/SM.
// 2-stage explicit prefetch; out[BEMB..2*BEMB) = mu.
__global__ void __launch_bounds__(256, 3)
k6_mu(const float* __restrict__ Wmu, const float* __restrict__ bmu,
      float* __restrict__ out){
  extern __shared__ float sm[];
  float2* sOd = (float2*)sm;          // [k][b] o2 duplicated
  const int tid = threadIdx.x;
  const int n0 = blockIdx.x * 256;
  const int ng = tid & 63, bg = tid >> 6;

  for (int idx = tid; idx < L2n*Bn; idx += 256){
    int k = idx >> 5, b = idx & 31;
    float v = g_o2[b*L2n + k];
    sOd[idx] = make_float2(v, v);
  }
  __syncthreads();

  ull acc[8][2];
  {
    float4 b4 = ((const float4*)(bmu + n0))[ng];
    #pragma unroll
    for (int j = 0; j < 8; ++j){ acc[j][0] = ((ull*)&b4)[0]; acc[j][1] = ((ull*)&b4)[1]; }
  }
  const float* wbase = Wmu + n0 + 4*ng;
  float4 w0 = *(const float4*)(wbase);
  float4 w1 = *(const float4*)(wbase + EMBn);
  for (int k = 0; k < L2n; k += 2){
    float4 c0 = w0, c1 = w1;
    if (k + 2 < L2n){
      w0 = *(const float4*)(wbase + (size_t)(k+2)*EMBn);
      w1 = *(const float4*)(wbase + (size_t)(k+3)*EMBn);
    }
    #pragma unroll
    for (int t = 0; t < 2; ++t){
      ull wa = t ? ((ull*)&c1)[0] : ((ull*)&c0)[0];
      ull wb = t ? ((ull*)&c1)[1] : ((ull*)&c0)[1];
      const ull* od = (const ull*)(sOd + (k+t)*Bn) + bg*8;
      #pragma unroll
      for (int j = 0; j < 8; ++j){
        ull o = od[j];
        acc[j][0] = fma2_(o, wa, acc[j][0]);
        acc[j][1] = fma2_(o, wb, acc[j][1]);
      }
    }
  }
  #pragma unroll
  for (int j = 0; j < 8; ++j){
    int b = bg*8 + j;
    float4 r;
    ((ull*)&r)[0] = acc[j][0];
    ((ull*)&r)[1] = acc[j][1];
    ((float4*)(out + BEMB + (size_t)b*EMBn + n0))[ng] = r;
  }
}

// ---------------- K6b: logvar + reparameterize -----------------------------
// out[2B..3B) = logvar; out[0..B) = eps*exp(0.5*lv) + mu (mu read from out)
__global__ void __launch_bounds__(256, 3)
k6_lv(const float* __restrict__ Wlv, const float* __restrict__ blv,
      const float* __restrict__ eps, float* __restrict__ out){
  extern __shared__ float sm[];
  float2* sOd = (float2*)sm;
  const int tid = threadIdx.x;
  const int n0 = blockIdx.x * 256;
  const int ng = tid & 63, bg = tid >> 6;

  for (int idx = tid; idx < L2n*Bn; idx += 256){
    int k = idx >> 5, b = idx & 31;
    float v = g_o2[b*L2n + k];
    sOd[idx] = make_float2(v, v);
  }
  __syncthreads();

  ull acc[8][2];
  {
    float4 b4 = ((const float4*)(blv + n0))[ng];
    #pragma unroll
    for (int j = 0; j < 8; ++j){ acc[j][0] = ((ull*)&b4)[0]; acc[j][1] = ((ull*)&b4)[1]; }
  }
  const float* wbase = Wlv + n0 + 4*ng;
  float4 w0 = *(const float4*)(wbase);
  float4 w1 = *(const float4*)(wbase + EMBn);
  for (int k = 0; k < L2n; k += 2){
    float4 c0 = w0, c1 = w1;
    if (k + 2 < L2n){
      w0 = *(const float4*)(wbase + (size_t)(k+2)*EMBn);
      w1 = *(const float4*)(wbase + (size_t)(k+3)*EMBn);
    }
    #pragma unroll
    for (int t = 0; t < 2; ++t){
      ull wa = t ? ((ull*)&c1)[0] : ((ull*)&c0)[0];
      ull wb = t ? ((ull*)&c1)[1] : ((ull*)&c0)[1];
      const ull* od = (const ull*)(sOd + (k+t)*Bn) + bg*8;
      #pragma unroll
      for (int j = 0; j < 8; ++j){
        ull o = od[j];
        acc[j][0] = fma2_(o, wa, acc[j][0]);
        acc[j][1] = fma2_(o, wb, acc[j][1]);
      }
    }
  }
  #pragma unroll
  for (int j = 0; j < 8; ++j){
    int b = bg*8 + j;
    float4 lv;
    ((ull*)&lv)[0] = acc[j][0];
    ((ull*)&lv)[1] = acc[j][1];
    ((float4*)(out + 2*BEMB + (size_t)b*EMBn + n0))[ng] = lv;
    float4 m4 = ((const float4*)(out + BEMB + (size_t)b*EMBn + n0))[ng];
    float4 e4 = ((const float4*)(eps + (size_t)b*EMBn + n0))[ng];
    float4 h;
    h.x = fmaf(e4.x, expf(0.5f*lv.x), m4.x);
    h.y = fmaf(e4.y, expf(0.5f*lv.y), m4.y);
    h.z = fmaf(e4.z, expf(0.5f*lv.z), m4.z);
    h.w = fmaf(e4.w, expf(0.5f*lv.w), m4.w);
    ((float4*)(out + (size_t)b*EMBn + n0))[ng] = h;
  }
}

// ---------------------------------------------------------------------------
extern "C" void kernel_launch(void* const* d_in, const int* in_sizes, int n_in,
                              void* d_out, int out_size) {
  const float* adj  = (const float*)d_in[0];
  const float* node = (const float*)d_in[1];
  const float* W0   = (const float*)d_in[2];
  const float* b0   = (const float*)d_in[3];
  const float* W2_0 = (const float*)d_in[4];
  const float* b2_0 = (const float*)d_in[5];
  const float* W1   = (const float*)d_in[6];
  const float* b1   = (const float*)d_in[7];
  const float* W2_1 = (const float*)d_in[8];
  const float* b2_1 = (const float*)d_in[9];
  const float* Wi   = (const float*)d_in[10];
  const float* bi   = (const float*)d_in[11];
  const float* Wj   = (const float*)d_in[12];
  const float* bj   = (const float*)d_in[13];
  const float* Wd1  = (const float*)d_in[14];
  const float* bd1  = (const float*)d_in[15];
  const float* Wd2  = (const float*)d_in[16];
  const float* bd2  = (const float*)d_in[17];
  const float* Wmu  = (const float*)d_in[18];
  const float* bmu  = (const float*)d_in[19];
  const float* Wlv  = (const float*)d_in[20];
  const float* blv  = (const float*)d_in[21];
  const float* eps  = (const float*)d_in[22];
  float* out = (float*)d_out;

  const int smem1 = (Vn*17 + 68*U1n + Mn*U1n + U1n + 32*257 + 32*68) * 4;
  const int smem2 = (F1n*U2n + U2n + 64*145) * 4;
  const int smem3 = (32*257 + 64*64 + F1n*U2n + U2n + 32*145) * 4;
  const int smem4 = (2*F2n*64 + 2*64 + 32*F2n) * 8 + 4*64*8;
  const int smem6 = L2n*Bn*8;

  cudaFuncSetAttribute(k1_gcl0, cudaFuncAttributeMaxDynamicSharedMemorySize, smem1);
  cudaFuncSetAttribute(k2_p1,   cudaFuncAttributeMaxDynamicSharedMemorySize, smem2);
  cudaFuncSetAttribute(k3_gcl1, cudaFuncAttributeMaxDynamicSharedMemorySize, smem3);
  cudaFuncSetAttribute(k4_pool, cudaFuncAttributeMaxDynamicSharedMemorySize, smem4);
  cudaFuncSetAttribute(k6_mu,   cudaFuncAttributeMaxDynamicSharedMemorySize, smem6);
  cudaFuncSetAttribute(k6_lv,   cudaFuncAttributeMaxDynamicSharedMemorySize, smem6);

  k1_gcl0<<<dim3(8, Bn), 256, smem1>>>(adj, node, W0, b0, W2_0, b2_0);
  k2_p1  <<<dim3(16, Bn), 256, smem2>>>(W1, b1);
  k3_gcl1<<<dim3(8, Bn), 256, smem3>>>(adj, node, W2_1, b2_1);
  k4_pool<<<dim3(8, Bn), 256, smem4>>>(Wi, bi, Wj, bj);
  k5_dense<<<Bn, 256>>>(Wd1, bd1, Wd2, bd2);
  k6_mu<<<EMBn/256, 256, smem6>>>(Wmu, bmu, out);
  k6_lv<<<EMBn/256, 256, smem6>>>(Wlv, blv, eps, out);
}